// round 5
// baseline (speedup 1.0000x reference)
#include <cuda_runtime.h>
#include <stdint.h>

#define N_BCH 8
#define N_ATM 10000
#define N_ELM 100
#define THREADS 512
#define NWARP  (THREADS / 32)
#define GRID_MAIN 296            // 2 CTAs per SM (148 SMs)

#define ELM_BYTES (N_BCH * N_ATM)                  // 80000
// smem layout (bytes)
#define SMEM_ACC   0                               // NWARP*256 floats = 16384
#define SMEM_LUT   (NWARP * 256 * 4)               // 128 float2 = 1024
#define SMEM_ELM   (SMEM_LUT + 1024)
#define SMEM_TOTAL (SMEM_ELM + ELM_BYTES)          // 97408 B -> 2 CTAs = 190.3 KB

// Global staging for the u8 element table (built once per launch by prepass).
__device__ uint8_t g_elm8[ELM_BYTES];

// ---------------------------------------------------------------------------
// Prepass: zero outputs, convert elm int32 -> uint8 (values < 100).
// ---------------------------------------------------------------------------
__global__ void prep_kernel(const int* __restrict__ elm, float* __restrict__ out)
{
    int tid = blockIdx.x * blockDim.x + threadIdx.x;
    if (tid < N_BCH) out[tid] = 0.0f;
    for (int i = tid; i < ELM_BYTES; i += gridDim.x * blockDim.x)
        g_elm8[i] = (uint8_t)elm[i];
}

// ---------------------------------------------------------------------------
// Main kernel: all gathers served from shared memory.
// ---------------------------------------------------------------------------
__device__ __forceinline__ void edge_op(int n, int i, int j, float s,
                                        const uint8_t* __restrict__ elm_s,
                                        const float2* __restrict__ lut,
                                        float* __restrict__ acc_base)
{
    int a = elm_s[n * N_ATM + i];
    int b = elm_s[n * N_ATM + j];
    float2 pa = lut[a];
    float2 pb = lut[b];
    float R   = pa.y + pb.y;
    float dis = sqrtf(s);
    if (dis < R) {
        float d = dis - R;
        acc_base[n << 5] += (pa.x + pb.x) * d * d;
    }
}

__global__ void __launch_bounds__(THREADS, 2)
close_penalty_kernel(const int4*  __restrict__ edge_n4,
                     const int4*  __restrict__ edge_i4,
                     const int4*  __restrict__ edge_j4,
                     const float4* __restrict__ sod4,
                     const int*   __restrict__ edge_n,
                     const int*   __restrict__ edge_i,
                     const int*   __restrict__ edge_j,
                     const float* __restrict__ sod,
                     const float* __restrict__ k,
                     const float* __restrict__ radius,
                     float* __restrict__ out,
                     int nvec, int E)
{
    extern __shared__ char smem[];
    float*   acc   = (float*)  (smem + SMEM_ACC);   // [warp][bin][lane]
    float2*  lut   = (float2*) (smem + SMEM_LUT);
    uint8_t* elm_s = (uint8_t*)(smem + SMEM_ELM);

    int tid  = threadIdx.x;
    int lane = tid & 31;
    int wid  = tid >> 5;

    if (tid < N_ELM) lut[tid] = make_float2(__ldg(&k[tid]), __ldg(&radius[tid]));
    #pragma unroll
    for (int i = tid; i < NWARP * 256; i += THREADS) acc[i] = 0.0f;

    // Copy 80 KB u8 element table into shared memory (16B chunks).
    {
        const int4* src = (const int4*)g_elm8;
        int4*       dst = (int4*)elm_s;
        for (int i = tid; i < ELM_BYTES / 16; i += THREADS)
            dst[i] = __ldg(&src[i]);
    }
    __syncthreads();

    float* acc_base = &acc[(wid << 8) | lane];   // + (n<<5) per edge

    int gtid   = blockIdx.x * blockDim.x + tid;
    int stride = gridDim.x * blockDim.x;

    int v = gtid;
    // 2x unrolled: 8 independent 16B streaming loads in flight per warp.
    for (; v + stride < nvec; v += 2 * stride) {
        int v2 = v + stride;
        int4   en0 = __ldcs(&edge_n4[v]);
        int4   ei0 = __ldcs(&edge_i4[v]);
        int4   ej0 = __ldcs(&edge_j4[v]);
        float4 s0  = __ldcs(&sod4[v]);
        int4   en1 = __ldcs(&edge_n4[v2]);
        int4   ei1 = __ldcs(&edge_i4[v2]);
        int4   ej1 = __ldcs(&edge_j4[v2]);
        float4 s1  = __ldcs(&sod4[v2]);

        edge_op(en0.x, ei0.x, ej0.x, s0.x, elm_s, lut, acc_base);
        edge_op(en0.y, ei0.y, ej0.y, s0.y, elm_s, lut, acc_base);
        edge_op(en0.z, ei0.z, ej0.z, s0.z, elm_s, lut, acc_base);
        edge_op(en0.w, ei0.w, ej0.w, s0.w, elm_s, lut, acc_base);
        edge_op(en1.x, ei1.x, ej1.x, s1.x, elm_s, lut, acc_base);
        edge_op(en1.y, ei1.y, ej1.y, s1.y, elm_s, lut, acc_base);
        edge_op(en1.z, ei1.z, ej1.z, s1.z, elm_s, lut, acc_base);
        edge_op(en1.w, ei1.w, ej1.w, s1.w, elm_s, lut, acc_base);
    }
    for (; v < nvec; v += stride) {
        int4   en = __ldcs(&edge_n4[v]);
        int4   ei = __ldcs(&edge_i4[v]);
        int4   ej = __ldcs(&edge_j4[v]);
        float4 s  = __ldcs(&sod4[v]);
        edge_op(en.x, ei.x, ej.x, s.x, elm_s, lut, acc_base);
        edge_op(en.y, ei.y, ej.y, s.y, elm_s, lut, acc_base);
        edge_op(en.z, ei.z, ej.z, s.z, elm_s, lut, acc_base);
        edge_op(en.w, ei.w, ej.w, s.w, elm_s, lut, acc_base);
    }

    // Scalar tail
    int t = nvec * 4 + gtid;
    if (t < E)
        edge_op(edge_n[t], edge_i[t], edge_j[t], sod[t], elm_s, lut, acc_base);

    __syncthreads();

    // Reduce: first 256 threads; thread owns (bin = tid>>5, lane).
    if (tid < 256) {
        int bin = tid >> 5;
        float sum = 0.0f;
        #pragma unroll
        for (int w = 0; w < NWARP; w++)
            sum += acc[(w << 8) + (bin << 5) + lane];
        #pragma unroll
        for (int off = 16; off > 0; off >>= 1)
            sum += __shfl_down_sync(0xFFFFFFFFu, sum, off);
        if (lane == 0)
            atomicAdd(&out[bin], sum);
    }
}

// ---------------------------------------------------------------------------
// Launch
// ---------------------------------------------------------------------------
extern "C" void kernel_launch(void* const* d_in, const int* in_sizes, int n_in,
                              void* d_out, int out_size)
{
    const int*   elm    = (const int*)  d_in[0];
    const int*   edge_n = (const int*)  d_in[1];
    const int*   edge_i = (const int*)  d_in[2];
    const int*   edge_j = (const int*)  d_in[3];
    const float* sod    = (const float*)d_in[4];
    const float* k      = (const float*)d_in[5];
    const float* radius = (const float*)d_in[6];
    float* out = (float*)d_out;

    int E    = in_sizes[1];
    int nvec = E >> 2;

    cudaFuncSetAttribute(close_penalty_kernel,
                         cudaFuncAttributeMaxDynamicSharedMemorySize, SMEM_TOTAL);

    prep_kernel<<<(ELM_BYTES + 255) / 256, 256>>>(elm, out);

    int grid = GRID_MAIN;
    int need = (nvec + THREADS - 1) / THREADS;
    if (need < grid) grid = need > 0 ? need : 1;

    close_penalty_kernel<<<grid, THREADS, SMEM_TOTAL>>>(
        (const int4*)edge_n, (const int4*)edge_i, (const int4*)edge_j,
        (const float4*)sod,
        edge_n, edge_i, edge_j, sod,
        k, radius,
        out, nvec, E);
}

// round 6
// speedup vs baseline: 1.0795x; 1.0795x over previous
#include <cuda_runtime.h>
#include <stdint.h>

#define N_BCH 8
#define N_ATM 10000
#define N_ELM 100
#define THREADS 256
#define GRID_MAIN 296            // 2 CTAs per SM (148 SMs)

#define ELM_BYTES (N_BCH * N_ATM)               // 80000
// smem layout (bytes)
#define SMEM_ACC   0                            // 8*256 floats = 8192 (used only at end)
#define SMEM_LUT   (8 * THREADS * 4)            // 128 float2 = 1024
#define SMEM_ELM   (SMEM_LUT + 1024)
#define SMEM_TOTAL (SMEM_ELM + ELM_BYTES)       // 89216 B

__device__ uint8_t g_elm8[ELM_BYTES];

__device__ __forceinline__ float fsqrt_approx(float x)
{
    float y;
    asm("sqrt.approx.f32 %0, %1;" : "=f"(y) : "f"(x));
    return y;
}

// ---------------------------------------------------------------------------
// Prepass: zero outputs, convert elm int32 -> uint8 (values < 100).
// ---------------------------------------------------------------------------
__global__ void prep_kernel(const int* __restrict__ elm, float* __restrict__ out)
{
    int tid = blockIdx.x * blockDim.x + threadIdx.x;
    if (tid < N_BCH) out[tid] = 0.0f;
    for (int i = tid; i < ELM_BYTES; i += gridDim.x * blockDim.x)
        g_elm8[i] = (uint8_t)elm[i];
}

// ---------------------------------------------------------------------------
// Per-edge work: smem gathers + register-bin accumulation (no smem RMW).
// ---------------------------------------------------------------------------
__device__ __forceinline__ void edge_op(int n, int i, int j, float s,
                                        const uint8_t* __restrict__ elm_s,
                                        const float2* __restrict__ lut,
                                        float* __restrict__ a)   // a[8] in regs
{
    int ea = elm_s[n * N_ATM + i];
    int eb = elm_s[n * N_ATM + j];
    float2 pa = lut[ea];
    float2 pb = lut[eb];
    float R   = pa.y + pb.y;
    float dis = fsqrt_approx(s);
    float d   = dis - R;
    float v   = (dis < R) ? (pa.x + pb.x) * d * d : 0.0f;

    // two-level predicated bin select: n = 4*hi + m
    float vlo = (n & 4) ? 0.0f : v;
    float vhi = (n & 4) ? v    : 0.0f;
    int   m   = n & 3;
    #pragma unroll
    for (int c = 0; c < 4; c++) {
        bool p = (m == c);
        a[c]     += p ? vlo : 0.0f;
        a[c + 4] += p ? vhi : 0.0f;
    }
}

__global__ void __launch_bounds__(THREADS, 2)
close_penalty_kernel(const int4*  __restrict__ edge_n4,
                     const int4*  __restrict__ edge_i4,
                     const int4*  __restrict__ edge_j4,
                     const float4* __restrict__ sod4,
                     const int*   __restrict__ edge_n,
                     const int*   __restrict__ edge_i,
                     const int*   __restrict__ edge_j,
                     const float* __restrict__ sod,
                     const float* __restrict__ k,
                     const float* __restrict__ radius,
                     float* __restrict__ out,
                     int nvec, int E)
{
    extern __shared__ char smem[];
    float*   accs  = (float*)  (smem + SMEM_ACC);
    float2*  lut   = (float2*) (smem + SMEM_LUT);
    uint8_t* elm_s = (uint8_t*)(smem + SMEM_ELM);

    int tid  = threadIdx.x;
    int lane = tid & 31;

    if (tid < N_ELM) lut[tid] = make_float2(__ldg(&k[tid]), __ldg(&radius[tid]));

    // Copy 80 KB u8 element table into shared memory (16B chunks).
    {
        const int4* src = (const int4*)g_elm8;
        int4*       dst = (int4*)elm_s;
        for (int i = tid; i < ELM_BYTES / 16; i += THREADS)
            dst[i] = __ldg(&src[i]);
    }
    __syncthreads();

    float a[8];
    #pragma unroll
    for (int b = 0; b < 8; b++) a[b] = 0.0f;

    int gtid   = blockIdx.x * blockDim.x + tid;
    int stride = gridDim.x * blockDim.x;

    int v = gtid;
    // 2x unrolled: 8 independent 16B streaming loads in flight per warp.
    for (; v + stride < nvec; v += 2 * stride) {
        int v2 = v + stride;
        int4   en0 = __ldcs(&edge_n4[v]);
        int4   ei0 = __ldcs(&edge_i4[v]);
        int4   ej0 = __ldcs(&edge_j4[v]);
        float4 s0  = __ldcs(&sod4[v]);
        int4   en1 = __ldcs(&edge_n4[v2]);
        int4   ei1 = __ldcs(&edge_i4[v2]);
        int4   ej1 = __ldcs(&edge_j4[v2]);
        float4 s1  = __ldcs(&sod4[v2]);

        edge_op(en0.x, ei0.x, ej0.x, s0.x, elm_s, lut, a);
        edge_op(en0.y, ei0.y, ej0.y, s0.y, elm_s, lut, a);
        edge_op(en0.z, ei0.z, ej0.z, s0.z, elm_s, lut, a);
        edge_op(en0.w, ei0.w, ej0.w, s0.w, elm_s, lut, a);
        edge_op(en1.x, ei1.x, ej1.x, s1.x, elm_s, lut, a);
        edge_op(en1.y, ei1.y, ej1.y, s1.y, elm_s, lut, a);
        edge_op(en1.z, ei1.z, ej1.z, s1.z, elm_s, lut, a);
        edge_op(en1.w, ei1.w, ej1.w, s1.w, elm_s, lut, a);
    }
    for (; v < nvec; v += stride) {
        int4   en = __ldcs(&edge_n4[v]);
        int4   ei = __ldcs(&edge_i4[v]);
        int4   ej = __ldcs(&edge_j4[v]);
        float4 s  = __ldcs(&sod4[v]);
        edge_op(en.x, ei.x, ej.x, s.x, elm_s, lut, a);
        edge_op(en.y, ei.y, ej.y, s.y, elm_s, lut, a);
        edge_op(en.z, ei.z, ej.z, s.z, elm_s, lut, a);
        edge_op(en.w, ei.w, ej.w, s.w, elm_s, lut, a);
    }

    // Scalar tail
    int t = nvec * 4 + gtid;
    if (t < E)
        edge_op(edge_n[t], edge_i[t], edge_j[t], sod[t], elm_s, lut, a);

    __syncthreads();   // elm_s dead from here; stage register bins

    #pragma unroll
    for (int b = 0; b < 8; b++)
        accs[b * THREADS + tid] = a[b];
    __syncthreads();

    // Reduce: thread t owns (bin = t>>5, lane); sum 8 chunks, shuffle-reduce.
    int bin = tid >> 5;
    float sum = 0.0f;
    #pragma unroll
    for (int w = 0; w < 8; w++)
        sum += accs[bin * THREADS + (w << 5) + lane];
    #pragma unroll
    for (int off = 16; off > 0; off >>= 1)
        sum += __shfl_down_sync(0xFFFFFFFFu, sum, off);
    if (lane == 0)
        atomicAdd(&out[bin], sum);
}

// ---------------------------------------------------------------------------
// Launch
// ---------------------------------------------------------------------------
extern "C" void kernel_launch(void* const* d_in, const int* in_sizes, int n_in,
                              void* d_out, int out_size)
{
    const int*   elm    = (const int*)  d_in[0];
    const int*   edge_n = (const int*)  d_in[1];
    const int*   edge_i = (const int*)  d_in[2];
    const int*   edge_j = (const int*)  d_in[3];
    const float* sod    = (const float*)d_in[4];
    const float* k      = (const float*)d_in[5];
    const float* radius = (const float*)d_in[6];
    float* out = (float*)d_out;

    int E    = in_sizes[1];
    int nvec = E >> 2;

    cudaFuncSetAttribute(close_penalty_kernel,
                         cudaFuncAttributeMaxDynamicSharedMemorySize, SMEM_TOTAL);

    prep_kernel<<<(ELM_BYTES + 255) / 256, 256>>>(elm, out);

    int grid = GRID_MAIN;
    int need = (nvec + THREADS - 1) / THREADS;
    if (need < grid) grid = need > 0 ? need : 1;

    close_penalty_kernel<<<grid, THREADS, SMEM_TOTAL>>>(
        (const int4*)edge_n, (const int4*)edge_i, (const int4*)edge_j,
        (const float4*)sod,
        edge_n, edge_i, edge_j, sod,
        k, radius,
        out, nvec, E);
}